// round 11
// baseline (speedup 1.0000x reference)
#include <cuda_runtime.h>
#include <cstdint>

#define BB  16
#define TQ  128
#define TK  256
#define DIN 64
#define HH  256
#define DV  256
#define NEGF (-1000000.0f)

#define HS   2            // h-split factor
#define HHH  (HH / HS)    // 128 h per partial CTA
#define QT   (TQ / 4)     // 32 q-tiles per batch

// Scratch
__device__ float g_qproj[BB * TQ * HH];            // 2 MB
__device__ float g_kprojT[BB * HH * TK];           // 4 MB
__device__ float g_part[HS * BB * QT * 4 * TK];    // 4 MB partial scores

__device__ __forceinline__ float tanha(float x) {
    float y;
    asm("tanh.approx.f32 %0, %1;" : "=f"(y) : "f"(x));
    return y;
}

__device__ __forceinline__ void cp16(uint32_t dst_smem, const void* src) {
    asm volatile("cp.async.ca.shared.global [%0], [%1], 16;\n"
                 :: "r"(dst_smem), "l"(src));
}

// ---------------------------------------------------------------------------
// Kernel 1: projections (unchanged). 8 rows per CTA, thread == hidden column.
// ---------------------------------------------------------------------------
__global__ __launch_bounds__(256) void proj_kernel(
    const float* __restrict__ queries, const float* __restrict__ keys,
    const float* __restrict__ wq, const float* __restrict__ wk)
{
    const int tid = threadIdx.x;
    const int blk = blockIdx.x;
    __shared__ __align__(16) float ins[8 * DIN];

    const float* W;
    const float* inbase;
    bool isQ = blk < (BB * TQ / 8);
    int b, r0;
    if (isQ) {
        b  = blk / (TQ / 8);
        r0 = (blk % (TQ / 8)) * 8;
        W  = wq;
        inbase = queries + (b * TQ + r0) * DIN;
    } else {
        int kb = blk - BB * TQ / 8;
        b  = kb / (TK / 8);
        r0 = (kb % (TK / 8)) * 8;
        W  = wk;
        inbase = keys + (b * TK + r0) * DIN;
    }
    ins[tid]       = inbase[tid];
    ins[tid + 256] = inbase[tid + 256];
    __syncthreads();

    float a[8];
    #pragma unroll
    for (int r = 0; r < 8; r++) a[r] = 0.f;

    #pragma unroll 8
    for (int d = 0; d < DIN; d++) {
        float w = W[d * HH + tid];
        #pragma unroll
        for (int r = 0; r < 8; r++)
            a[r] = fmaf(ins[r * DIN + d], w, a[r]);
    }

    if (isQ) {
        float* o = g_qproj + (b * TQ + r0) * HH + tid;
        #pragma unroll
        for (int r = 0; r < 8; r++) o[r * HH] = a[r];
    } else {
        float* o = g_kprojT + (size_t)b * HH * TK + tid * TK + r0;
        *(float4*)(o + 0) = make_float4(a[0], a[1], a[2], a[3]);
        *(float4*)(o + 4) = make_float4(a[4], a[5], a[6], a[7]);
    }
}

// ---------------------------------------------------------------------------
// Kernel 2: partial scores over one h-half.
// CTA = (batch, 4-q-row tile, h-half). Thread == one k. Warps with all keys
// masked skip the tanh block. Partials written to g_part.
// ---------------------------------------------------------------------------
#define CHUNK_H  16
#define NCHUNK_P (HHH / CHUNK_H)   // 8

__global__ __launch_bounds__(256) void score_partial_kernel(
    const int* __restrict__ valid_lens, const float* __restrict__ wv)
{
    const int tid = threadIdx.x;
    const int blk = blockIdx.x;               // b*64 + qt*2 + hs
    const int b   = blk >> 6;
    const int qt  = (blk & 63) >> 1;
    const int hs  = blk & 1;
    const int q0  = qt * 4;

    __shared__ __align__(16) float kbuf[2][CHUNK_H][TK];   // 32 KB
    __shared__ __align__(16) float qs[4][HHH];             // 2 KB
    __shared__ __align__(16) float wvs[HHH];               // 0.5 KB

    const int vl = valid_lens[b];
    const bool active = (tid < vl);           // warp-uniform for tail warps

    // load this h-half of q rows and wv
    {
        int r = tid >> 7, hh = tid & 127;     // 2 elems per thread
        qs[r + 0][hh] = g_qproj[(b * TQ + q0 + r + 0) * HH + hs * HHH + hh];
        qs[r + 2][hh] = g_qproj[(b * TQ + q0 + r + 2) * HH + hs * HHH + hh];
        if (tid < HHH) wvs[tid] = wv[hs * HHH + tid];
    }

    const float* kTb = g_kprojT + (size_t)b * HH * TK + (size_t)hs * HHH * TK;

    // prefetch chunk 0
    {
        uint32_t base = (uint32_t)__cvta_generic_to_shared(&kbuf[0][0][0]);
        #pragma unroll
        for (int j = 0; j < 4; j++) {
            int s = tid + 256 * j;
            cp16(base + s * 16, kTb + s * 4);
        }
        asm volatile("cp.async.commit_group;");
    }
    __syncthreads();

    float acc[4] = {0.f, 0.f, 0.f, 0.f};

    #pragma unroll 1
    for (int c = 0; c < NCHUNK_P; c++) {
        const int bufi = c & 1;
        if (c + 1 < NCHUNK_P) {
            uint32_t base = (uint32_t)__cvta_generic_to_shared(&kbuf[bufi ^ 1][0][0]);
            const float* src = kTb + (c + 1) * CHUNK_H * TK;
            #pragma unroll
            for (int j = 0; j < 4; j++) {
                int s = tid + 256 * j;
                cp16(base + s * 16, src + s * 4);
            }
            asm volatile("cp.async.commit_group;");
            asm volatile("cp.async.wait_group 1;");
        } else {
            asm volatile("cp.async.wait_group 0;");
        }
        __syncthreads();

        if (active) {
            #pragma unroll
            for (int hh = 0; hh < CHUNK_H; hh += 4) {
                const int h = c * CHUNK_H + hh;
                float k0 = kbuf[bufi][hh + 0][tid];
                float k1 = kbuf[bufi][hh + 1][tid];
                float k2 = kbuf[bufi][hh + 2][tid];
                float k3 = kbuf[bufi][hh + 3][tid];
                float4 wv4 = *(const float4*)&wvs[h];
                #pragma unroll
                for (int r = 0; r < 4; r++) {
                    float4 q4 = *(const float4*)&qs[r][h];
                    acc[r] = fmaf(wv4.x, tanha(q4.x + k0), acc[r]);
                    acc[r] = fmaf(wv4.y, tanha(q4.y + k1), acc[r]);
                    acc[r] = fmaf(wv4.z, tanha(q4.z + k2), acc[r]);
                    acc[r] = fmaf(wv4.w, tanha(q4.w + k3), acc[r]);
                }
            }
        }
        __syncthreads();
    }

    float* po = g_part + (size_t)(((hs * BB + b) * QT + qt) * 4) * TK + tid;
    #pragma unroll
    for (int r = 0; r < 4; r++) po[r * TK] = acc[r];
}

// ---------------------------------------------------------------------------
// Kernel 3: combine partials + masked softmax + attn @ V.
// CTA = (batch, 4-q-row tile). Thread == one k (then one v-column).
// ---------------------------------------------------------------------------
__global__ __launch_bounds__(256) void softmax_av_kernel(
    const float* __restrict__ values, const int* __restrict__ valid_lens,
    float* __restrict__ out)
{
    const int tid  = threadIdx.x;
    const int b    = blockIdx.x >> 5;
    const int qt   = blockIdx.x & 31;
    const int q0   = qt * 4;
    const int lane = tid & 31, wid = tid >> 5;

    __shared__ __align__(16) float attnS[4][TK];
    __shared__ float redm[4][8], reds[4][8];

    const int vl = valid_lens[b];
    const bool active = (tid < vl);

    const float* p0 = g_part + (size_t)(((0 * BB + b) * QT + qt) * 4) * TK + tid;
    const float* p1 = g_part + (size_t)(((1 * BB + b) * QT + qt) * 4) * TK + tid;

    float s[4];
    #pragma unroll
    for (int r = 0; r < 4; r++) {
        float v = p0[r * TK] + p1[r * TK];
        s[r] = active ? v : NEGF;
        float mm = s[r];
        #pragma unroll
        for (int o = 16; o; o >>= 1) mm = fmaxf(mm, __shfl_xor_sync(0xffffffffu, mm, o));
        if (lane == 0) redm[r][wid] = mm;
    }
    __syncthreads();
    float p[4];
    #pragma unroll
    for (int r = 0; r < 4; r++) {
        float mm = redm[r][0];
        #pragma unroll
        for (int i = 1; i < 8; i++) mm = fmaxf(mm, redm[r][i]);
        p[r] = __expf(s[r] - mm);              // vl==0 -> uniform
        float ss = p[r];
        #pragma unroll
        for (int o = 16; o; o >>= 1) ss += __shfl_xor_sync(0xffffffffu, ss, o);
        if (lane == 0) reds[r][wid] = ss;
    }
    __syncthreads();
    #pragma unroll
    for (int r = 0; r < 4; r++) {
        float ss = reds[r][0];
        #pragma unroll
        for (int i = 1; i < 8; i++) ss += reds[r][i];
        attnS[r][tid] = p[r] * (1.0f / ss);
    }
    __syncthreads();

    // out[r][v=tid] = sum_k attn[r][k] * V[k][tid]; masked weights are exact 0
    const int kend = (vl == 0) ? TK : min(TK, (vl + 3) & ~3);
    const float* Vp = values + (size_t)b * TK * DV + tid;
    float o4[4] = {0.f, 0.f, 0.f, 0.f};
    float n0 = Vp[0 * DV], n1 = Vp[1 * DV], n2 = Vp[2 * DV], n3 = Vp[3 * DV];
    #pragma unroll 2
    for (int k = 0; k < kend; k += 4) {
        float v0 = n0, v1 = n1, v2 = n2, v3 = n3;
        if (k + 4 < kend) {
            n0 = Vp[(k + 4) * DV]; n1 = Vp[(k + 5) * DV];
            n2 = Vp[(k + 6) * DV]; n3 = Vp[(k + 7) * DV];
        }
        #pragma unroll
        for (int r = 0; r < 4; r++) {
            float4 a4 = *(const float4*)&attnS[r][k];
            o4[r] = fmaf(a4.x, v0, o4[r]);
            o4[r] = fmaf(a4.y, v1, o4[r]);
            o4[r] = fmaf(a4.z, v2, o4[r]);
            o4[r] = fmaf(a4.w, v3, o4[r]);
        }
    }
    #pragma unroll
    for (int r = 0; r < 4; r++)
        out[(b * TQ + q0 + r) * DV + tid] = o4[r];
}

extern "C" void kernel_launch(void* const* d_in, const int* in_sizes, int n_in,
                              void* d_out, int out_size)
{
    const float* queries    = (const float*)d_in[0];
    const float* keys       = (const float*)d_in[1];
    const float* values     = (const float*)d_in[2];
    const int*   valid_lens = (const int*)  d_in[3];
    const float* wq         = (const float*)d_in[4];
    const float* wk         = (const float*)d_in[5];
    const float* wv         = (const float*)d_in[6];
    float*       out        = (float*)d_out;

    proj_kernel<<<BB * (TQ + TK) / 8, 256>>>(queries, keys, wq, wk);
    score_partial_kernel<<<BB * QT * HS, 256>>>(valid_lens, wv);
    softmax_av_kernel<<<BB * QT, 256>>>(values, valid_lens, out);
}